// round 3
// baseline (speedup 1.0000x reference)
#include <cuda_runtime.h>
#include <cstdint>

typedef unsigned long long ull;

#define B_   4
#define S_   2048
#define DM_  2048
#define DS_  64
#define REC_ 336   // floats per token record: q[0:64] k[64:128] a[128:192] amk[192:256] v[256:320] g/h/c[320:323] pad

// ---------------- f32x2 packed helpers (Blackwell) ----------------
__device__ __forceinline__ ull fma2(ull a, ull b, ull c) {
    ull d; asm("fma.rn.f32x2 %0,%1,%2,%3;" : "=l"(d) : "l"(a), "l"(b), "l"(c)); return d;
}
__device__ __forceinline__ ull mul2(ull a, ull b) {
    ull d; asm("mul.rn.f32x2 %0,%1,%2;" : "=l"(d) : "l"(a), "l"(b)); return d;
}
__device__ __forceinline__ ull pack2(float lo, float hi) {
    ull d; asm("mov.b64 %0, {%1,%2};" : "=l"(d) : "f"(lo), "f"(hi)); return d;
}
__device__ __forceinline__ float2 unpack2(ull a) {
    float lo, hi; asm("mov.b64 {%0,%1}, %2;" : "=f"(lo), "=f"(hi) : "l"(a));
    return make_float2(lo, hi);
}

// ---------------- cp.async helpers ----------------
__device__ __forceinline__ void cp_async16(void* smem, const void* gmem) {
    uint32_t s = (uint32_t)__cvta_generic_to_shared(smem);
    asm volatile("cp.async.cg.shared.global [%0], [%1], 16;" :: "r"(s), "l"(gmem) : "memory");
}
#define CP_COMMIT()  asm volatile("cp.async.commit_group;" ::: "memory")
#define CP_WAIT3()   asm volatile("cp.async.wait_group 3;" ::: "memory")

// ---------------- scratch ----------------
__device__ float g_raw[B_ * S_ * 256];   // [m][256]: k v q r_pre
__device__ float g_inp[B_ * S_ * REC_];
__device__ float g_km [B_ * S_ * DS_];   // km per token (consumed by ghc)
__device__ float g_y  [B_ * S_ * DS_];

// =====================================================================
// Kernel A: projection GEMM. g_raw[m][nt*64+n] = sum_k x[m][k]*W_nt[n][k]
// =====================================================================
#define BM 64
#define BN 64
#define BK 32

__global__ void __launch_bounds__(256) proj_gemm(
    const float* __restrict__ x,
    const float* __restrict__ Wk, const float* __restrict__ Wv,
    const float* __restrict__ Wq, const float* __restrict__ Wa)
{
    __shared__ __align__(16) float As[BK][BM + 4];
    __shared__ __align__(16) float Bs[BK][BN + 4];

    const int mt = blockIdx.x;
    const int nt = blockIdx.y;
    const float* W = (nt == 0) ? Wk : (nt == 1) ? Wv : (nt == 2) ? Wq : Wa;

    const int tid  = threadIdx.x;
    const int lrow = tid >> 2;           // 0..63
    const int lk   = (tid & 3) * 4;      // 0,4,8,12 (+16 second half)
    const float* xg = x + (size_t)(mt * BM + lrow) * DM_ + lk;
    const float* wg = W + (size_t)lrow * DM_ + lk;

    const int tn4 = (tid & 15) * 4;
    const int tm4 = (tid >> 4) * 4;

    ull acc[4][2];
    #pragma unroll
    for (int i = 0; i < 4; i++) { acc[i][0] = 0ull; acc[i][1] = 0ull; }

    float4 av0 = *(const float4*)xg;
    float4 av1 = *(const float4*)(xg + 16);
    float4 bv0 = *(const float4*)wg;
    float4 bv1 = *(const float4*)(wg + 16);

    for (int k0 = 0; k0 < DM_; k0 += BK) {
        __syncthreads();
        As[lk + 0][lrow] = av0.x; As[lk + 1][lrow] = av0.y;
        As[lk + 2][lrow] = av0.z; As[lk + 3][lrow] = av0.w;
        As[lk + 16][lrow] = av1.x; As[lk + 17][lrow] = av1.y;
        As[lk + 18][lrow] = av1.z; As[lk + 19][lrow] = av1.w;
        Bs[lk + 0][lrow] = bv0.x; Bs[lk + 1][lrow] = bv0.y;
        Bs[lk + 2][lrow] = bv0.z; Bs[lk + 3][lrow] = bv0.w;
        Bs[lk + 16][lrow] = bv1.x; Bs[lk + 17][lrow] = bv1.y;
        Bs[lk + 18][lrow] = bv1.z; Bs[lk + 19][lrow] = bv1.w;
        if (k0 + BK < DM_) {
            av0 = *(const float4*)(xg + k0 + BK);
            av1 = *(const float4*)(xg + k0 + BK + 16);
            bv0 = *(const float4*)(wg + k0 + BK);
            bv1 = *(const float4*)(wg + k0 + BK + 16);
        }
        __syncthreads();
        #pragma unroll
        for (int kk = 0; kk < BK; kk++) {
            ulonglong2 bb = *(const ulonglong2*)&Bs[kk][tn4];
            float4 a4 = *(const float4*)&As[kk][tm4];
            ull p0 = pack2(a4.x, a4.x), p1 = pack2(a4.y, a4.y);
            ull p2 = pack2(a4.z, a4.z), p3 = pack2(a4.w, a4.w);
            acc[0][0] = fma2(p0, bb.x, acc[0][0]); acc[0][1] = fma2(p0, bb.y, acc[0][1]);
            acc[1][0] = fma2(p1, bb.x, acc[1][0]); acc[1][1] = fma2(p1, bb.y, acc[1][1]);
            acc[2][0] = fma2(p2, bb.x, acc[2][0]); acc[2][1] = fma2(p2, bb.y, acc[2][1]);
            acc[3][0] = fma2(p3, bb.x, acc[3][0]); acc[3][1] = fma2(p3, bb.y, acc[3][1]);
        }
    }

    #pragma unroll
    for (int i = 0; i < 4; i++) {
        int m = mt * BM + tm4 + i;
        #pragma unroll
        for (int j = 0; j < 2; j++) {
            float2 f = unpack2(acc[i][j]);
            *(float2*)&g_raw[(size_t)m * 256 + nt * 64 + tn4 + 2 * j] = f;
        }
    }
}

// =====================================================================
// Kernel B: per-token prep. One warp per token.
// Writes record q,k,a,v,c ; km -> g_km (amk/g/h filled by ghc_kernel)
// =====================================================================
__global__ void __launch_bounds__(256) prep_kernel(
    const float* __restrict__ Wa_b, const float* __restrict__ lam)
{
    const int g    = blockIdx.x * 8 + (threadIdx.x >> 5);
    const int lane = threadIdx.x & 31;
    const float* r_ = g_raw + (size_t)g * 256;

    float k0 = r_[lane],        k1 = r_[lane + 32];
    float v0 = r_[64 + lane],   v1 = r_[96 + lane];
    float q0 = r_[128 + lane],  q1 = r_[160 + lane];
    float z0 = r_[192 + lane] + Wa_b[lane];
    float z1 = r_[224 + lane] + Wa_b[lane + 32];

    float kn = k0 * k0 + k1 * k1;
    #pragma unroll
    for (int m = 1; m < 32; m <<= 1) kn += __shfl_xor_sync(~0u, kn, m);
    float kinv = 1.0f / fmaxf(sqrtf(kn), 1e-12f);
    k0 *= kinv; k1 *= kinv;

    float qn = q0 * q0 + q1 * q1;
    #pragma unroll
    for (int m = 1; m < 32; m <<= 1) qn += __shfl_xor_sync(~0u, qn, m);
    float qinv = 1.0f / fmaxf(sqrtf(qn), 1e-12f);
    q0 *= qinv; q1 *= qinv;

    float la0 = logf(1.0f / (1.0f + expf(-lam[lane])) + 1e-8f);
    float la1 = logf(1.0f / (1.0f + expf(-lam[lane + 32])) + 1e-8f);
    float rr0 = 1.0f / (1.0f + expf(-z0));
    float rr1 = 1.0f / (1.0f + expf(-z1));
    float al0 = expf(8.0f * rr0 * la0);
    float al1 = expf(8.0f * rr1 * la1);
    float km0 = k0 * (1.0f - al0), km1 = k1 * (1.0f - al1);

    float c = q0 * km0 + q1 * km1;
    #pragma unroll
    for (int m = 1; m < 32; m <<= 1) c += __shfl_xor_sync(~0u, c, m);

    float* o = g_inp + (size_t)g * REC_;
    o[lane] = q0;         o[lane + 32] = q1;
    o[64 + lane] = k0;    o[96 + lane] = k1;
    o[128 + lane] = al0;  o[160 + lane] = al1;
    o[256 + lane] = v0;   o[288 + lane] = v1;
    float* km = g_km + (size_t)g * DS_;
    km[lane] = km0; km[lane + 32] = km1;
    if (lane == 0) { o[322] = c; o[323] = 0.0f; }
}

// =====================================================================
// Kernel B2: cross-token products. amk_t = a_t*km_{t-1},
// g_t = q_t·km_{t-1}, h_t = k_t·km_{t-1}.  t==0 -> zeros.
// =====================================================================
__global__ void __launch_bounds__(256) ghc_kernel()
{
    const int g    = blockIdx.x * 8 + (threadIdx.x >> 5);
    const int lane = threadIdx.x & 31;
    const int t    = g & (S_ - 1);
    float* cur = g_inp + (size_t)g * REC_;

    float m0 = 0.0f, m1 = 0.0f;
    if (t > 0) {
        const float* km = g_km + (size_t)(g - 1) * DS_;
        m0 = km[lane]; m1 = km[lane + 32];
    }
    float q0 = cur[lane],       q1 = cur[lane + 32];
    float k0 = cur[64 + lane],  k1 = cur[96 + lane];
    float a0 = cur[128 + lane], a1 = cur[160 + lane];

    cur[192 + lane] = a0 * m0;
    cur[224 + lane] = a1 * m1;

    float gq = q0 * m0 + q1 * m1;
    float gh = k0 * m0 + k1 * m1;
    #pragma unroll
    for (int m = 1; m < 32; m <<= 1) {
        gq += __shfl_xor_sync(~0u, gq, m);
        gh += __shfl_xor_sync(~0u, gh, m);
    }
    if (lane == 0) { cur[320] = gq; cur[321] = gh; }
}

// =====================================================================
// Kernel C: sequential scan. 4 CTAs x 512 threads.
// Thread (v=tid>>3, kg=tid&7) owns Ha[kg*8..kg*8+7][v] as 4 f32x2.
// Maintains ONLY Ha = a_i (.) H_{i-1}. Cross-warp P/Q/R via smem atomics.
// =====================================================================
__global__ void __launch_bounds__(512, 1) scan_kernel()
{
    __shared__ __align__(16) float stage[8][REC_];
    __shared__ __align__(16) float PQR[4][4];

    const int b    = blockIdx.x;
    const int tid  = threadIdx.x;
    const int v    = tid >> 3;
    const int kg   = tid & 7;
    const int ko   = kg * 8;
    const int lane = tid & 31;

    const float* base = g_inp + (size_t)b * S_ * REC_;
    float* yb = g_y + (size_t)b * S_ * DS_;

    if (tid < 16) ((float*)PQR)[tid] = 0.0f;

    #pragma unroll
    for (int t = 0; t < 5; t++) {
        if (tid < 84) cp_async16(&stage[t][tid * 4], base + (size_t)t * REC_ + tid * 4);
        CP_COMMIT();
    }
    CP_WAIT3();
    __syncthreads();

    ull Ha[4], qc[4];
    #pragma unroll
    for (int j = 0; j < 4; j++) Ha[j] = 0ull;
    {
        ulonglong2 t0 = *(const ulonglong2*)&stage[0][ko];
        ulonglong2 t1 = *(const ulonglong2*)&stage[0][ko + 4];
        qc[0] = t0.x; qc[1] = t0.y; qc[2] = t1.x; qc[3] = t1.y;
    }
    float v_cur = stage[0][256 + v];
    float s_prev = 0.0f, w_prev = 0.0f, C_cur = 0.0f;
    {   // step-0 partials: u = v_0, w_{-1}=0
        float pp = v_cur * v_cur;
        pp += __shfl_xor_sync(~0u, pp, 8);
        pp += __shfl_xor_sync(~0u, pp, 16);
        if (lane == 0) atomicAdd(&PQR[0][0], pp);
    }
    __syncthreads();

    for (int i = 0; i < S_; i++) {
        const float* rc = stage[i & 7];
        const float* rn = stage[(i + 1) & 7];

        if (tid < 84 && i + 5 < S_)
            cp_async16(&stage[(i + 5) & 7][tid * 4],
                       base + (size_t)(i + 5) * REC_ + tid * 4);
        CP_COMMIT();
        CP_WAIT3();

        // ---- scalar head (serial chain) ----
        float4 pqr = *(const float4*)PQR[i & 3];
        float4 ghc = *(const float4*)&rc[320];          // g,h,c
        if (tid < 4) PQR[(i + 2) & 3][tid] = 0.0f;
        float swp = s_prev * w_prev;
        float sg  = s_prev * ghc.x;
        float err = pqr.x + sg * (sg * pqr.z - 2.0f * pqr.y);
        float s   = __fdividef(1.0f, 1.0f + __expf(-err * 0.99999899f));
        float w   = (v_cur - C_cur) - s_prev * ghc.y * w_prev;
        ull sw2 = pack2(swp, swp);

        // ---- Ha_i = a_i*Ha_{i-1} + swp*amk_i ----
        {
            ulonglong2 a0 = *(const ulonglong2*)&rc[128 + ko];
            ulonglong2 a1 = *(const ulonglong2*)&rc[128 + ko + 4];
            ulonglong2 m0 = *(const ulonglong2*)&rc[192 + ko];
            ulonglong2 m1 = *(const ulonglong2*)&rc[192 + ko + 4];
            Ha[0] = fma2(a0.x, Ha[0], mul2(m0.x, sw2));
            Ha[1] = fma2(a0.y, Ha[1], mul2(m0.y, sw2));
            Ha[2] = fma2(a1.x, Ha[2], mul2(m1.x, sw2));
            Ha[3] = fma2(a1.y, Ha[3], mul2(m1.y, sw2));
        }

        // ---- y-dot: q_i . Ha_i ----
        ull ya = mul2(qc[0], Ha[0]);
        ya = fma2(qc[1], Ha[1], ya);
        ya = fma2(qc[2], Ha[2], ya);
        ya = fma2(qc[3], Ha[3], ya);

        // ---- next-step dots: A = q_{i+1}.Ha_i, C = k_{i+1}.Ha_i ----
        ulonglong2 q0 = *(const ulonglong2*)&rn[ko];
        ulonglong2 q1 = *(const ulonglong2*)&rn[ko + 4];
        ulonglong2 k0 = *(const ulonglong2*)&rn[64 + ko];
        ulonglong2 k1 = *(const ulonglong2*)&rn[64 + ko + 4];
        ull aa = mul2(q0.x, Ha[0]);
        aa = fma2(q0.y, Ha[1], aa);
        aa = fma2(q1.x, Ha[2], aa);
        aa = fma2(q1.y, Ha[3], aa);
        ull cd = mul2(k0.x, Ha[0]);
        cd = fma2(k0.y, Ha[1], cd);
        cd = fma2(k1.x, Ha[2], cd);
        cd = fma2(k1.y, Ha[3], cd);
        qc[0] = q0.x; qc[1] = q0.y; qc[2] = q1.x; qc[3] = q1.y;

        float2 fy = unpack2(ya); float yv = fy.x + fy.y;
        float2 fa = unpack2(aa); float Af = fa.x + fa.y;
        float2 fc = unpack2(cd); float Cf = fc.x + fc.y;
        yv += __shfl_xor_sync(~0u, yv, 1);
        Af += __shfl_xor_sync(~0u, Af, 1);
        Cf += __shfl_xor_sync(~0u, Cf, 1);
        yv += __shfl_xor_sync(~0u, yv, 2);
        Af += __shfl_xor_sync(~0u, Af, 2);
        Cf += __shfl_xor_sync(~0u, Cf, 2);
        yv += __shfl_xor_sync(~0u, yv, 4);
        Af += __shfl_xor_sync(~0u, Af, 4);
        Cf += __shfl_xor_sync(~0u, Cf, 4);

        if (kg == 0) yb[(size_t)i * DS_ + v] = yv + ghc.z * s * w;

        // ---- partials for step i+1 ----
        float vn = rn[256 + v];
        float u  = vn - Af;
        float pp = u * u, qq = u * w, rr = w * w;
        pp += __shfl_xor_sync(~0u, pp, 8);
        qq += __shfl_xor_sync(~0u, qq, 8);
        rr += __shfl_xor_sync(~0u, rr, 8);
        pp += __shfl_xor_sync(~0u, pp, 16);
        qq += __shfl_xor_sync(~0u, qq, 16);
        rr += __shfl_xor_sync(~0u, rr, 16);
        if (lane == 0) {
            atomicAdd(&PQR[(i + 1) & 3][0], pp);
            atomicAdd(&PQR[(i + 1) & 3][1], qq);
            atomicAdd(&PQR[(i + 1) & 3][2], rr);
        }

        s_prev = s; w_prev = w; C_cur = Cf; v_cur = vn;
        __syncthreads();
    }
}

// =====================================================================
// Kernel D: RMS-norm(y)*norm_w @ Wo^T -> out[8192][2048]
// =====================================================================
__global__ void __launch_bounds__(256) out_gemm(
    const float* __restrict__ norm_w, const float* __restrict__ Wo,
    float* __restrict__ out)
{
    __shared__ __align__(16) float ys[32 * 64];
    __shared__ __align__(16) float wos[64 * 128];
    __shared__ float rs[32];
    __shared__ float nws[64];

    const int tid = threadIdx.x;
    const int m0 = blockIdx.y * 32;
    const int n0 = blockIdx.x * 128;

    for (int i = tid * 4; i < 2048; i += 1024)
        *(float4*)&ys[i] = *(const float4*)&g_y[(size_t)m0 * 64 + i];
    if (tid < 64) nws[tid] = norm_w[tid];
    {
        int n  = tid & 127;
        int vb = tid >> 7;
        #pragma unroll
        for (int q = 0; q < 8; q++) {
            int v4 = vb * 8 + q;
            float4 w = *(const float4*)&Wo[(size_t)(n0 + n) * 64 + v4 * 4];
            wos[(v4 * 4 + 0) * 128 + n] = w.x;
            wos[(v4 * 4 + 1) * 128 + n] = w.y;
            wos[(v4 * 4 + 2) * 128 + n] = w.z;
            wos[(v4 * 4 + 3) * 128 + n] = w.w;
        }
    }
    __syncthreads();

    {
        int r = tid >> 3, p = tid & 7;
        float sum = 0.0f;
        #pragma unroll
        for (int j = 0; j < 8; j++) { float x = ys[r * 64 + p * 8 + j]; sum += x * x; }
        sum += __shfl_xor_sync(~0u, sum, 1);
        sum += __shfl_xor_sync(~0u, sum, 2);
        sum += __shfl_xor_sync(~0u, sum, 4);
        if (p == 0) rs[r] = rsqrtf(sum * (1.0f / 64.0f) + 1e-6f);
    }
    __syncthreads();
    for (int i = tid; i < 2048; i += 256)
        ys[i] = ys[i] * rs[i >> 6] * nws[i & 63];
    __syncthreads();

    const int tn = tid & 31;
    const int tm = tid >> 5;
    float acc[4][4];
    #pragma unroll
    for (int i = 0; i < 4; i++)
        #pragma unroll
        for (int j = 0; j < 4; j++) acc[i][j] = 0.0f;

    #pragma unroll 8
    for (int vv = 0; vv < 64; vv++) {
        float b0 = wos[vv * 128 + tn];
        float b1 = wos[vv * 128 + tn + 32];
        float b2 = wos[vv * 128 + tn + 64];
        float b3 = wos[vv * 128 + tn + 96];
        #pragma unroll
        for (int i = 0; i < 4; i++) {
            float a = ys[(tm * 4 + i) * 64 + vv];
            acc[i][0] += a * b0; acc[i][1] += a * b1;
            acc[i][2] += a * b2; acc[i][3] += a * b3;
        }
    }
    #pragma unroll
    for (int i = 0; i < 4; i++) {
        size_t row = (size_t)(m0 + tm * 4 + i) * 2048 + n0 + tn;
        #pragma unroll
        for (int j = 0; j < 4; j++) out[row + 32 * j] = acc[i][j];
    }
}

// =====================================================================
extern "C" void kernel_launch(void* const* d_in, const int* in_sizes, int n_in,
                              void* d_out, int out_size)
{
    const float* x      = (const float*)d_in[0];
    const float* Wk     = (const float*)d_in[1];
    const float* Wv     = (const float*)d_in[2];
    const float* Wq     = (const float*)d_in[3];
    const float* Wa_w   = (const float*)d_in[4];
    const float* Wa_b   = (const float*)d_in[5];
    const float* lam    = (const float*)d_in[6];
    const float* norm_w = (const float*)d_in[7];
    const float* Wo     = (const float*)d_in[8];
    float* out = (float*)d_out;

    proj_gemm<<<dim3(128, 4), 256>>>(x, Wk, Wv, Wq, Wa_w);
    prep_kernel<<<1024, 256>>>(Wa_b, lam);
    ghc_kernel<<<1024, 256>>>();
    scan_kernel<<<4, 512>>>();
    out_gemm<<<dim3(16, 256), 256>>>(norm_w, Wo, out);
}

// round 6
// speedup vs baseline: 1.4254x; 1.4254x over previous
#include <cuda_runtime.h>
#include <cstdint>

typedef unsigned long long ull;

#define B_   4
#define S_   2048
#define DM_  2048
#define DS_  64
#define REC_ 336   // q[0:64] k[64:128] a[128:192] amk[192:256] v[256:320] g,h,c[320:323]

// ---------------- f32x2 packed helpers ----------------
__device__ __forceinline__ ull fma2(ull a, ull b, ull c) {
    ull d; asm("fma.rn.f32x2 %0,%1,%2,%3;" : "=l"(d) : "l"(a), "l"(b), "l"(c)); return d;
}
__device__ __forceinline__ ull mul2(ull a, ull b) {
    ull d; asm("mul.rn.f32x2 %0,%1,%2;" : "=l"(d) : "l"(a), "l"(b)); return d;
}
__device__ __forceinline__ ull pack2(float lo, float hi) {
    ull d; asm("mov.b64 %0, {%1,%2};" : "=l"(d) : "f"(lo), "f"(hi)); return d;
}
__device__ __forceinline__ float2 unpack2(ull a) {
    float lo, hi; asm("mov.b64 {%0,%1}, %2;" : "=f"(lo), "=f"(hi) : "l"(a));
    return make_float2(lo, hi);
}

// ---------------- cp.async ----------------
__device__ __forceinline__ void cp_async16(void* smem, const void* gmem) {
    uint32_t s = (uint32_t)__cvta_generic_to_shared(smem);
    asm volatile("cp.async.cg.shared.global [%0], [%1], 16;" :: "r"(s), "l"(gmem) : "memory");
}
#define CP_COMMIT()  asm volatile("cp.async.commit_group;" ::: "memory")
#define CP_WAIT3()   asm volatile("cp.async.wait_group 3;" ::: "memory")
#define BAR0()       asm volatile("bar.sync 0;" ::: "memory")

// ---------------- scratch ----------------
__device__ float g_raw[B_ * S_ * 256];
__device__ float g_inp[B_ * S_ * REC_];
__device__ float g_km [B_ * S_ * DS_];
__device__ float g_y  [B_ * S_ * DS_];

// =====================================================================
// Kernel A: projection GEMM (proven in R3)
// =====================================================================
#define BM 64
#define BN 64
#define BK 32

__global__ void __launch_bounds__(256) proj_gemm(
    const float* __restrict__ x,
    const float* __restrict__ Wk, const float* __restrict__ Wv,
    const float* __restrict__ Wq, const float* __restrict__ Wa)
{
    __shared__ __align__(16) float As[BK][BM + 4];
    __shared__ __align__(16) float Bs[BK][BN + 4];

    const int mt = blockIdx.x;
    const int nt = blockIdx.y;
    const float* W = (nt == 0) ? Wk : (nt == 1) ? Wv : (nt == 2) ? Wq : Wa;

    const int tid  = threadIdx.x;
    const int lrow = tid >> 2;
    const int lk   = (tid & 3) * 4;
    const float* xg = x + (size_t)(mt * BM + lrow) * DM_ + lk;
    const float* wg = W + (size_t)lrow * DM_ + lk;

    const int tn4 = (tid & 15) * 4;
    const int tm4 = (tid >> 4) * 4;

    ull acc[4][2];
    #pragma unroll
    for (int i = 0; i < 4; i++) { acc[i][0] = 0ull; acc[i][1] = 0ull; }

    float4 av0 = *(const float4*)xg;
    float4 av1 = *(const float4*)(xg + 16);
    float4 bv0 = *(const float4*)wg;
    float4 bv1 = *(const float4*)(wg + 16);

    for (int k0 = 0; k0 < DM_; k0 += BK) {
        __syncthreads();
        As[lk + 0][lrow] = av0.x; As[lk + 1][lrow] = av0.y;
        As[lk + 2][lrow] = av0.z; As[lk + 3][lrow] = av0.w;
        As[lk + 16][lrow] = av1.x; As[lk + 17][lrow] = av1.y;
        As[lk + 18][lrow] = av1.z; As[lk + 19][lrow] = av1.w;
        Bs[lk + 0][lrow] = bv0.x; Bs[lk + 1][lrow] = bv0.y;
        Bs[lk + 2][lrow] = bv0.z; Bs[lk + 3][lrow] = bv0.w;
        Bs[lk + 16][lrow] = bv1.x; Bs[lk + 17][lrow] = bv1.y;
        Bs[lk + 18][lrow] = bv1.z; Bs[lk + 19][lrow] = bv1.w;
        if (k0 + BK < DM_) {
            av0 = *(const float4*)(xg + k0 + BK);
            av1 = *(const float4*)(xg + k0 + BK + 16);
            bv0 = *(const float4*)(wg + k0 + BK);
            bv1 = *(const float4*)(wg + k0 + BK + 16);
        }
        __syncthreads();
        #pragma unroll
        for (int kk = 0; kk < BK; kk++) {
            ulonglong2 bb = *(const ulonglong2*)&Bs[kk][tn4];
            float4 a4 = *(const float4*)&As[kk][tm4];
            ull p0 = pack2(a4.x, a4.x), p1 = pack2(a4.y, a4.y);
            ull p2 = pack2(a4.z, a4.z), p3 = pack2(a4.w, a4.w);
            acc[0][0] = fma2(p0, bb.x, acc[0][0]); acc[0][1] = fma2(p0, bb.y, acc[0][1]);
            acc[1][0] = fma2(p1, bb.x, acc[1][0]); acc[1][1] = fma2(p1, bb.y, acc[1][1]);
            acc[2][0] = fma2(p2, bb.x, acc[2][0]); acc[2][1] = fma2(p2, bb.y, acc[2][1]);
            acc[3][0] = fma2(p3, bb.x, acc[3][0]); acc[3][1] = fma2(p3, bb.y, acc[3][1]);
        }
    }

    #pragma unroll
    for (int i = 0; i < 4; i++) {
        int m = mt * BM + tm4 + i;
        #pragma unroll
        for (int j = 0; j < 2; j++) {
            float2 f = unpack2(acc[i][j]);
            *(float2*)&g_raw[(size_t)m * 256 + nt * 64 + tn4 + 2 * j] = f;
        }
    }
}

// =====================================================================
// Kernel B: per-token prep (proven in R3)
// =====================================================================
__global__ void __launch_bounds__(256) prep_kernel(
    const float* __restrict__ Wa_b, const float* __restrict__ lam)
{
    const int g    = blockIdx.x * 8 + (threadIdx.x >> 5);
    const int lane = threadIdx.x & 31;
    const float* r_ = g_raw + (size_t)g * 256;

    float k0 = r_[lane],        k1 = r_[lane + 32];
    float v0 = r_[64 + lane],   v1 = r_[96 + lane];
    float q0 = r_[128 + lane],  q1 = r_[160 + lane];
    float z0 = r_[192 + lane] + Wa_b[lane];
    float z1 = r_[224 + lane] + Wa_b[lane + 32];

    float kn = k0 * k0 + k1 * k1;
    #pragma unroll
    for (int m = 1; m < 32; m <<= 1) kn += __shfl_xor_sync(~0u, kn, m);
    float kinv = 1.0f / fmaxf(sqrtf(kn), 1e-12f);
    k0 *= kinv; k1 *= kinv;

    float qn = q0 * q0 + q1 * q1;
    #pragma unroll
    for (int m = 1; m < 32; m <<= 1) qn += __shfl_xor_sync(~0u, qn, m);
    float qinv = 1.0f / fmaxf(sqrtf(qn), 1e-12f);
    q0 *= qinv; q1 *= qinv;

    float la0 = logf(1.0f / (1.0f + expf(-lam[lane])) + 1e-8f);
    float la1 = logf(1.0f / (1.0f + expf(-lam[lane + 32])) + 1e-8f);
    float rr0 = 1.0f / (1.0f + expf(-z0));
    float rr1 = 1.0f / (1.0f + expf(-z1));
    float al0 = expf(8.0f * rr0 * la0);
    float al1 = expf(8.0f * rr1 * la1);
    float km0 = k0 * (1.0f - al0), km1 = k1 * (1.0f - al1);

    float c = q0 * km0 + q1 * km1;
    #pragma unroll
    for (int m = 1; m < 32; m <<= 1) c += __shfl_xor_sync(~0u, c, m);

    float* o = g_inp + (size_t)g * REC_;
    o[lane] = q0;         o[lane + 32] = q1;
    o[64 + lane] = k0;    o[96 + lane] = k1;
    o[128 + lane] = al0;  o[160 + lane] = al1;
    o[256 + lane] = v0;   o[288 + lane] = v1;
    float* km = g_km + (size_t)g * DS_;
    km[lane] = km0; km[lane + 32] = km1;
    if (lane == 0) { o[322] = c; o[323] = 0.0f; }
}

// =====================================================================
// Kernel B2: amk_t = a_t*km_{t-1}, g_t = q_t.km_{t-1}, h_t = k_t.km_{t-1}
// =====================================================================
__global__ void __launch_bounds__(256) ghc_kernel()
{
    const int g    = blockIdx.x * 8 + (threadIdx.x >> 5);
    const int lane = threadIdx.x & 31;
    const int t    = g & (S_ - 1);
    float* cur = g_inp + (size_t)g * REC_;

    float m0 = 0.0f, m1 = 0.0f;
    if (t > 0) {
        const float* km = g_km + (size_t)(g - 1) * DS_;
        m0 = km[lane]; m1 = km[lane + 32];
    }
    float q0 = cur[lane],       q1 = cur[lane + 32];
    float k0 = cur[64 + lane],  k1 = cur[96 + lane];
    float a0 = cur[128 + lane], a1 = cur[160 + lane];

    cur[192 + lane] = a0 * m0;
    cur[224 + lane] = a1 * m1;

    float gq = q0 * m0 + q1 * m1;
    float gh = k0 * m0 + k1 * m1;
    #pragma unroll
    for (int m = 1; m < 32; m <<= 1) {
        gq += __shfl_xor_sync(~0u, gq, m);
        gh += __shfl_xor_sync(~0u, gh, m);
    }
    if (lane == 0) { cur[320] = gq; cur[321] = gh; }
}

// =====================================================================
// Kernel C: warp-specialized scan, single bar.sync 0 per step.
// 4 CTAs x 288 threads. Warps 0-7 vector, warp 8 sequencer.
// All cross-role deps are (i-1)->(i), resolved by the closing barrier.
// =====================================================================
__device__ __forceinline__ void ld8(ull* d, const float* p) {
    ulonglong2 t0 = *(const ulonglong2*)(p);
    ulonglong2 t1 = *(const ulonglong2*)(p + 4);
    ulonglong2 t2 = *(const ulonglong2*)(p + 8);
    ulonglong2 t3 = *(const ulonglong2*)(p + 12);
    d[0] = t0.x; d[1] = t0.y; d[2] = t1.x; d[3] = t1.y;
    d[4] = t2.x; d[5] = t2.y; d[6] = t3.x; d[7] = t3.y;
}

__global__ void __launch_bounds__(288, 1) scan_kernel()
{
    __shared__ __align__(16) float  stage[8][REC_];
    __shared__ __align__(16) float2 swbuf[2][64];   // (sw, sw) per v
    __shared__ __align__(16) float2 ACbuf[2][64];   // (A, C) per v
    __shared__ float ybuf[2][64];                   // q.Ha per v

    const int b   = blockIdx.x;
    const int tid = threadIdx.x;
    const float* base = g_inp + (size_t)b * S_ * REC_;
    float* yb = g_y + (size_t)b * S_ * DS_;

    if (tid < 64) {
        swbuf[0][tid] = make_float2(0.0f, 0.0f);
        ACbuf[0][tid] = make_float2(0.0f, 0.0f);
    }
    #pragma unroll
    for (int t = 0; t < 5; t++) {
        if (tid < 84) cp_async16(&stage[t][tid * 4], base + (size_t)t * REC_ + tid * 4);
        CP_COMMIT();
    }
    CP_WAIT3();
    __syncthreads();

    if (tid < 256) {
        // ===== vector warps: Ha update + 3 dots =====
        const int v  = tid >> 2;
        const int kg = tid & 3;
        const int ko = kg * 16;

        ull Ha[8];
        #pragma unroll
        for (int j = 0; j < 8; j++) Ha[j] = 0ull;

        for (int i = 0; i < S_; i++) {
            const float* rc = stage[i & 7];
            const float* rn = stage[(i + 1) & 7];

            if (tid < 84 && i + 5 < S_)
                cp_async16(&stage[(i + 5) & 7][tid * 4],
                           base + (size_t)(i + 5) * REC_ + tid * 4);
            CP_COMMIT();

            // sw_i published by sequencer in step i-1 (visible via closing bar)
            ull sw2 = *(const ull*)&swbuf[i & 1][v];

            ull a8[8], mk8[8], q8[8];
            ld8(a8,  rc + 128 + ko);
            ld8(mk8, rc + 192 + ko);
            ld8(q8,  rc + ko);

            // Ha_i = a_i (.) Ha_{i-1} + sw_i * amk_i
            #pragma unroll
            for (int j = 0; j < 8; j++)
                Ha[j] = fma2(a8[j], Ha[j], mul2(mk8[j], sw2));

            // y-dot q_i . Ha_i (two chains)
            ull ya0 = mul2(q8[0], Ha[0]);
            ull ya1 = mul2(q8[1], Ha[1]);
            #pragma unroll
            for (int j = 2; j < 8; j += 2) {
                ya0 = fma2(q8[j],     Ha[j],     ya0);
                ya1 = fma2(q8[j + 1], Ha[j + 1], ya1);
            }

            // next-step dots A_{i+1} = q_{i+1}.Ha, C_{i+1} = k_{i+1}.Ha
            ull qn8[8], kn8[8];
            ld8(qn8, rn + ko);
            ld8(kn8, rn + 64 + ko);
            ull aa0 = mul2(qn8[0], Ha[0]);
            ull aa1 = mul2(qn8[1], Ha[1]);
            ull cc0 = mul2(kn8[0], Ha[0]);
            ull cc1 = mul2(kn8[1], Ha[1]);
            #pragma unroll
            for (int j = 2; j < 8; j += 2) {
                aa0 = fma2(qn8[j],     Ha[j],     aa0);
                aa1 = fma2(qn8[j + 1], Ha[j + 1], aa1);
                cc0 = fma2(kn8[j],     Ha[j],     cc0);
                cc1 = fma2(kn8[j + 1], Ha[j + 1], cc1);
            }

            float2 fy0 = unpack2(ya0), fy1 = unpack2(ya1);
            float2 fa0 = unpack2(aa0), fa1 = unpack2(aa1);
            float2 fc0 = unpack2(cc0), fc1 = unpack2(cc1);
            float yv = (fy0.x + fy0.y) + (fy1.x + fy1.y);
            float Af = (fa0.x + fa0.y) + (fa1.x + fa1.y);
            float Cf = (fc0.x + fc0.y) + (fc1.x + fc1.y);
            yv += __shfl_xor_sync(~0u, yv, 1);
            Af += __shfl_xor_sync(~0u, Af, 1);
            Cf += __shfl_xor_sync(~0u, Cf, 1);
            yv += __shfl_xor_sync(~0u, yv, 2);
            Af += __shfl_xor_sync(~0u, Af, 2);
            Cf += __shfl_xor_sync(~0u, Cf, 2);

            if (kg == 0) {
                ACbuf[(i + 1) & 1][v] = make_float2(Af, Cf);
                ybuf[i & 1][v] = yv;
            }
            CP_WAIT3();
            BAR0();
        }
    } else {
        // ===== sequencer warp: scalar chain + y writeback =====
        const int lane = tid - 256;
        float w0 = 0.0f, w1 = 0.0f, sprev = 0.0f, cprev = 0.0f;

        for (int i = 0; i < S_; i++) {
            const float* rc = stage[i & 7];

            float2 ac0 = ACbuf[i & 1][lane];
            float2 ac1 = ACbuf[i & 1][lane + 32];
            float v0 = rc[256 + lane], v1 = rc[288 + lane];
            float4 ghc = *(const float4*)&rc[320];   // g, h, c

            // y_{i-1} (off critical path; uses pre-update state)
            if (i > 0) {
                float ct = cprev * sprev;
                yb[(size_t)(i - 1) * DS_ + lane]      = ybuf[(i + 1) & 1][lane]      + ct * w0;
                yb[(size_t)(i - 1) * DS_ + lane + 32] = ybuf[(i + 1) & 1][lane + 32] + ct * w1;
            }

            float sg = sprev * ghc.x;
            float sh = sprev * ghc.y;
            float r0 = v0 - ac0.x - sg * w0;
            float r1 = v1 - ac1.x - sg * w1;
            float e = r0 * r0 + r1 * r1;
            e += __shfl_xor_sync(~0u, e, 1);
            e += __shfl_xor_sync(~0u, e, 2);
            e += __shfl_xor_sync(~0u, e, 4);
            e += __shfl_xor_sync(~0u, e, 8);
            e += __shfl_xor_sync(~0u, e, 16);
            // sigmoid(e * 0.99999899) = 0.5 * tanh(e * 0.499999495) + 0.5
            float s;
            asm("tanh.approx.f32 %0, %1;" : "=f"(s) : "f"(e * 0.499999495f));
            s = fmaf(0.5f, s, 0.5f);

            w0 = (v0 - ac0.y) - sh * w0;
            w1 = (v1 - ac1.y) - sh * w1;
            sprev = s; cprev = ghc.z;
            float sw0 = s * w0, sw1 = s * w1;
            swbuf[(i + 1) & 1][lane]      = make_float2(sw0, sw0);
            swbuf[(i + 1) & 1][lane + 32] = make_float2(sw1, sw1);
            BAR0();
        }
        // final y_{S-1}
        float ct = cprev * sprev;
        yb[(size_t)(S_ - 1) * DS_ + lane]      = ybuf[(S_ - 1) & 1][lane]      + ct * w0;
        yb[(size_t)(S_ - 1) * DS_ + lane + 32] = ybuf[(S_ - 1) & 1][lane + 32] + ct * w1;
    }
}

// =====================================================================
// Kernel D: RMS-norm(y)*norm_w @ Wo^T -> out (proven in R3)
// =====================================================================
__global__ void __launch_bounds__(256) out_gemm(
    const float* __restrict__ norm_w, const float* __restrict__ Wo,
    float* __restrict__ out)
{
    __shared__ __align__(16) float ys[32 * 64];
    __shared__ __align__(16) float wos[64 * 128];
    __shared__ float rs[32];
    __shared__ float nws[64];

    const int tid = threadIdx.x;
    const int m0 = blockIdx.y * 32;
    const int n0 = blockIdx.x * 128;

    for (int i = tid * 4; i < 2048; i += 1024)
        *(float4*)&ys[i] = *(const float4*)&g_y[(size_t)m0 * 64 + i];
    if (tid < 64) nws[tid] = norm_w[tid];
    {
        int n  = tid & 127;
        int vb = tid >> 7;
        #pragma unroll
        for (int q = 0; q < 8; q++) {
            int v4 = vb * 8 + q;
            float4 w = *(const float4*)&Wo[(size_t)(n0 + n) * 64 + v4 * 4];
            wos[(v4 * 4 + 0) * 128 + n] = w.x;
            wos[(v4 * 4 + 1) * 128 + n] = w.y;
            wos[(v4 * 4 + 2) * 128 + n] = w.z;
            wos[(v4 * 4 + 3) * 128 + n] = w.w;
        }
    }
    __syncthreads();

    {
        int r = tid >> 3, p = tid & 7;
        float sum = 0.0f;
        #pragma unroll
        for (int j = 0; j < 8; j++) { float x = ys[r * 64 + p * 8 + j]; sum += x * x; }
        sum += __shfl_xor_sync(~0u, sum, 1);
        sum += __shfl_xor_sync(~0u, sum, 2);
        sum += __shfl_xor_sync(~0u, sum, 4);
        if (p == 0) rs[r] = rsqrtf(sum * (1.0f / 64.0f) + 1e-6f);
    }
    __syncthreads();
    for (int i = tid; i < 2048; i += 256)
        ys[i] = ys[i] * rs[i >> 6] * nws[i & 63];
    __syncthreads();

    const int tn = tid & 31;
    const int tm = tid >> 5;
    float acc[4][4];
    #pragma unroll
    for (int i = 0; i < 4; i++)
        #pragma unroll
        for (int j = 0; j < 4; j++) acc[i][j] = 0.0f;

    #pragma unroll 8
    for (int vv = 0; vv < 64; vv++) {
        float b0 = wos[vv * 128 + tn];
        float b1 = wos[vv * 128 + tn + 32];
        float b2 = wos[vv * 128 + tn + 64];
        float b3 = wos[vv * 128 + tn + 96];
        #pragma unroll
        for (int i = 0; i < 4; i++) {
            float a = ys[(tm * 4 + i) * 64 + vv];
            acc[i][0] += a * b0; acc[i][1] += a * b1;
            acc[i][2] += a * b2; acc[i][3] += a * b3;
        }
    }
    #pragma unroll
    for (int i = 0; i < 4; i++) {
        size_t row = (size_t)(m0 + tm * 4 + i) * 2048 + n0 + tn;
        #pragma unroll
        for (int j = 0; j < 4; j++) out[row + 32 * j] = acc[i][j];
    }
}

// =====================================================================
extern "C" void kernel_launch(void* const* d_in, const int* in_sizes, int n_in,
                              void* d_out, int out_size)
{
    const float* x      = (const float*)d_in[0];
    const float* Wk     = (const float*)d_in[1];
    const float* Wv     = (const float*)d_in[2];
    const float* Wq     = (const float*)d_in[3];
    const float* Wa_w   = (const float*)d_in[4];
    const float* Wa_b   = (const float*)d_in[5];
    const float* lam    = (const float*)d_in[6];
    const float* norm_w = (const float*)d_in[7];
    const float* Wo     = (const float*)d_in[8];
    float* out = (float*)d_out;

    proj_gemm<<<dim3(128, 4), 256>>>(x, Wk, Wv, Wq, Wa_w);
    prep_kernel<<<1024, 256>>>(Wa_b, lam);
    ghc_kernel<<<1024, 256>>>();
    scan_kernel<<<4, 288>>>();
    out_gemm<<<dim3(16, 256), 256>>>(norm_w, Wo, out);
}

// round 7
// speedup vs baseline: 1.5137x; 1.0620x over previous
#include <cuda_runtime.h>
#include <cstdint>

typedef unsigned long long ull;

#define B_   4
#define S_   2048
#define DM_  2048
#define DS_  64
#define REC_ 400   // q[0:64] k[64:128] qa[128:192] a[192:256] amk[256:320] v[320:384] g,h,c,g2[384:388] pad->400

// ---------------- f32x2 packed helpers ----------------
__device__ __forceinline__ ull fma2(ull a, ull b, ull c) {
    ull d; asm("fma.rn.f32x2 %0,%1,%2,%3;" : "=l"(d) : "l"(a), "l"(b), "l"(c)); return d;
}
__device__ __forceinline__ ull mul2(ull a, ull b) {
    ull d; asm("mul.rn.f32x2 %0,%1,%2;" : "=l"(d) : "l"(a), "l"(b)); return d;
}
__device__ __forceinline__ ull pack2(float lo, float hi) {
    ull d; asm("mov.b64 %0, {%1,%2};" : "=l"(d) : "f"(lo), "f"(hi)); return d;
}
__device__ __forceinline__ float2 unpack2(ull a) {
    float lo, hi; asm("mov.b64 {%0,%1}, %2;" : "=f"(lo), "=f"(hi) : "l"(a));
    return make_float2(lo, hi);
}

// ---------------- cp.async ----------------
__device__ __forceinline__ void cp_async16(void* smem, const void* gmem) {
    uint32_t s = (uint32_t)__cvta_generic_to_shared(smem);
    asm volatile("cp.async.cg.shared.global [%0], [%1], 16;" :: "r"(s), "l"(gmem) : "memory");
}
#define CP_COMMIT()  asm volatile("cp.async.commit_group;" ::: "memory")
#define CP_WAIT3()   asm volatile("cp.async.wait_group 3;" ::: "memory")
#define BAR0()       asm volatile("bar.sync 0;" ::: "memory")

// ---------------- scratch ----------------
__device__ float g_raw[B_ * S_ * 256];
__device__ float g_inp[B_ * S_ * REC_];
__device__ float g_km [B_ * S_ * DS_];
__device__ float g_y  [B_ * S_ * DS_];

// =====================================================================
// Kernel A: projection GEMM (proven)
// =====================================================================
#define BM 64
#define BN 64
#define BK 32

__global__ void __launch_bounds__(256) proj_gemm(
    const float* __restrict__ x,
    const float* __restrict__ Wk, const float* __restrict__ Wv,
    const float* __restrict__ Wq, const float* __restrict__ Wa)
{
    __shared__ __align__(16) float As[BK][BM + 4];
    __shared__ __align__(16) float Bs[BK][BN + 4];

    const int mt = blockIdx.x;
    const int nt = blockIdx.y;
    const float* W = (nt == 0) ? Wk : (nt == 1) ? Wv : (nt == 2) ? Wq : Wa;

    const int tid  = threadIdx.x;
    const int lrow = tid >> 2;
    const int lk   = (tid & 3) * 4;
    const float* xg = x + (size_t)(mt * BM + lrow) * DM_ + lk;
    const float* wg = W + (size_t)lrow * DM_ + lk;

    const int tn4 = (tid & 15) * 4;
    const int tm4 = (tid >> 4) * 4;

    ull acc[4][2];
    #pragma unroll
    for (int i = 0; i < 4; i++) { acc[i][0] = 0ull; acc[i][1] = 0ull; }

    float4 av0 = *(const float4*)xg;
    float4 av1 = *(const float4*)(xg + 16);
    float4 bv0 = *(const float4*)wg;
    float4 bv1 = *(const float4*)(wg + 16);

    for (int k0 = 0; k0 < DM_; k0 += BK) {
        __syncthreads();
        As[lk + 0][lrow] = av0.x; As[lk + 1][lrow] = av0.y;
        As[lk + 2][lrow] = av0.z; As[lk + 3][lrow] = av0.w;
        As[lk + 16][lrow] = av1.x; As[lk + 17][lrow] = av1.y;
        As[lk + 18][lrow] = av1.z; As[lk + 19][lrow] = av1.w;
        Bs[lk + 0][lrow] = bv0.x; Bs[lk + 1][lrow] = bv0.y;
        Bs[lk + 2][lrow] = bv0.z; Bs[lk + 3][lrow] = bv0.w;
        Bs[lk + 16][lrow] = bv1.x; Bs[lk + 17][lrow] = bv1.y;
        Bs[lk + 18][lrow] = bv1.z; Bs[lk + 19][lrow] = bv1.w;
        if (k0 + BK < DM_) {
            av0 = *(const float4*)(xg + k0 + BK);
            av1 = *(const float4*)(xg + k0 + BK + 16);
            bv0 = *(const float4*)(wg + k0 + BK);
            bv1 = *(const float4*)(wg + k0 + BK + 16);
        }
        __syncthreads();
        #pragma unroll
        for (int kk = 0; kk < BK; kk++) {
            ulonglong2 bb = *(const ulonglong2*)&Bs[kk][tn4];
            float4 a4 = *(const float4*)&As[kk][tm4];
            ull p0 = pack2(a4.x, a4.x), p1 = pack2(a4.y, a4.y);
            ull p2 = pack2(a4.z, a4.z), p3 = pack2(a4.w, a4.w);
            acc[0][0] = fma2(p0, bb.x, acc[0][0]); acc[0][1] = fma2(p0, bb.y, acc[0][1]);
            acc[1][0] = fma2(p1, bb.x, acc[1][0]); acc[1][1] = fma2(p1, bb.y, acc[1][1]);
            acc[2][0] = fma2(p2, bb.x, acc[2][0]); acc[2][1] = fma2(p2, bb.y, acc[2][1]);
            acc[3][0] = fma2(p3, bb.x, acc[3][0]); acc[3][1] = fma2(p3, bb.y, acc[3][1]);
        }
    }

    #pragma unroll
    for (int i = 0; i < 4; i++) {
        int m = mt * BM + tm4 + i;
        #pragma unroll
        for (int j = 0; j < 2; j++) {
            float2 f = unpack2(acc[i][j]);
            *(float2*)&g_raw[(size_t)m * 256 + nt * 64 + tn4 + 2 * j] = f;
        }
    }
}

// =====================================================================
// Kernel B: per-token prep. Writes q,k,qa,a,v,c ; km -> g_km.
// =====================================================================
__global__ void __launch_bounds__(256) prep_kernel(
    const float* __restrict__ Wa_b, const float* __restrict__ lam)
{
    const int g    = blockIdx.x * 8 + (threadIdx.x >> 5);
    const int lane = threadIdx.x & 31;
    const float* r_ = g_raw + (size_t)g * 256;

    float k0 = r_[lane],        k1 = r_[lane + 32];
    float v0 = r_[64 + lane],   v1 = r_[96 + lane];
    float q0 = r_[128 + lane],  q1 = r_[160 + lane];
    float z0 = r_[192 + lane] + Wa_b[lane];
    float z1 = r_[224 + lane] + Wa_b[lane + 32];

    float kn = k0 * k0 + k1 * k1;
    #pragma unroll
    for (int m = 1; m < 32; m <<= 1) kn += __shfl_xor_sync(~0u, kn, m);
    float kinv = 1.0f / fmaxf(sqrtf(kn), 1e-12f);
    k0 *= kinv; k1 *= kinv;

    float qn = q0 * q0 + q1 * q1;
    #pragma unroll
    for (int m = 1; m < 32; m <<= 1) qn += __shfl_xor_sync(~0u, qn, m);
    float qinv = 1.0f / fmaxf(sqrtf(qn), 1e-12f);
    q0 *= qinv; q1 *= qinv;

    float la0 = logf(1.0f / (1.0f + expf(-lam[lane])) + 1e-8f);
    float la1 = logf(1.0f / (1.0f + expf(-lam[lane + 32])) + 1e-8f);
    float rr0 = 1.0f / (1.0f + expf(-z0));
    float rr1 = 1.0f / (1.0f + expf(-z1));
    float al0 = expf(8.0f * rr0 * la0);
    float al1 = expf(8.0f * rr1 * la1);
    float km0 = k0 * (1.0f - al0), km1 = k1 * (1.0f - al1);

    float c = q0 * km0 + q1 * km1;
    #pragma unroll
    for (int m = 1; m < 32; m <<= 1) c += __shfl_xor_sync(~0u, c, m);

    float* o = g_inp + (size_t)g * REC_;
    o[lane] = q0;               o[lane + 32] = q1;
    o[64 + lane] = k0;          o[96 + lane] = k1;
    o[128 + lane] = q0 * al0;   o[160 + lane] = q1 * al1;   // qa
    o[192 + lane] = al0;        o[224 + lane] = al1;        // a
    o[320 + lane] = v0;         o[352 + lane] = v1;         // v
    float* km = g_km + (size_t)g * DS_;
    km[lane] = km0; km[lane + 32] = km1;
    if (lane == 0) o[386] = c;
}

// =====================================================================
// Kernel B2: amk = a (.) km_{t-1};  g = q.km_{t-1}, h = k.km_{t-1},
// g2 = qa.km_{t-1}.  t==0 -> zeros.
// =====================================================================
__global__ void __launch_bounds__(256) ghc_kernel()
{
    const int g    = blockIdx.x * 8 + (threadIdx.x >> 5);
    const int lane = threadIdx.x & 31;
    const int t    = g & (S_ - 1);
    float* cur = g_inp + (size_t)g * REC_;

    float m0 = 0.0f, m1 = 0.0f;
    if (t > 0) {
        const float* km = g_km + (size_t)(g - 1) * DS_;
        m0 = km[lane]; m1 = km[lane + 32];
    }
    float q0 = cur[lane],        q1 = cur[lane + 32];
    float k0 = cur[64 + lane],   k1 = cur[96 + lane];
    float y0 = cur[128 + lane],  y1 = cur[160 + lane];   // qa
    float a0 = cur[192 + lane],  a1 = cur[224 + lane];

    cur[256 + lane] = a0 * m0;
    cur[288 + lane] = a1 * m1;

    float gq = q0 * m0 + q1 * m1;
    float gh = k0 * m0 + k1 * m1;
    float g2 = y0 * m0 + y1 * m1;
    #pragma unroll
    for (int m = 1; m < 32; m <<= 1) {
        gq += __shfl_xor_sync(~0u, gq, m);
        gh += __shfl_xor_sync(~0u, gh, m);
        g2 += __shfl_xor_sync(~0u, g2, m);
    }
    if (lane == 0) { cur[384] = gq; cur[385] = gh; cur[387] = g2; }
}

// =====================================================================
// Kernel C: warp-specialized scan, partial-STS reduction (no vector shfl).
// 4 CTAs x 288 threads. Warps 0-7 vector, warp 8 sequencer.
// =====================================================================
__device__ __forceinline__ void ld8(ull* d, const float* p) {
    ulonglong2 t0 = *(const ulonglong2*)(p);
    ulonglong2 t1 = *(const ulonglong2*)(p + 4);
    ulonglong2 t2 = *(const ulonglong2*)(p + 8);
    ulonglong2 t3 = *(const ulonglong2*)(p + 12);
    d[0] = t0.x; d[1] = t0.y; d[2] = t1.x; d[3] = t1.y;
    d[4] = t2.x; d[5] = t2.y; d[6] = t3.x; d[7] = t3.y;
}

__global__ void __launch_bounds__(288, 1) scan_kernel()
{
    __shared__ __align__(16) float  stage[8][REC_];
    __shared__ __align__(16) float4 part[2][64 * 5];   // [buf][v*5 + kg] (pad 80B/v: conflict-floor LDS)
    __shared__ __align__(16) float2 swbuf[2][64];      // (sw, sw) per v

    const int b   = blockIdx.x;
    const int tid = threadIdx.x;
    const float* base = g_inp + (size_t)b * S_ * REC_;
    float* yb = g_y + (size_t)b * S_ * DS_;

    if (tid < 64) swbuf[0][tid] = make_float2(0.0f, 0.0f);
    if (tid < 256) part[0][(tid >> 2) * 5 + (tid & 3)] = make_float4(0.f, 0.f, 0.f, 0.f);

    #pragma unroll
    for (int t = 0; t < 5; t++) {
        if (tid < 100) cp_async16(&stage[t][tid * 4], base + (size_t)t * REC_ + tid * 4);
        CP_COMMIT();
    }
    CP_WAIT3();
    __syncthreads();

    if (tid < 256) {
        // ===== vector warps: Ha update + 3 dots -> STS partials =====
        const int v  = tid >> 2;
        const int kg = tid & 3;
        const int ko = kg * 16;

        ull Ha[8];
        #pragma unroll
        for (int j = 0; j < 8; j++) Ha[j] = 0ull;

        for (int i = 0; i < S_; i++) {
            const float* rc = stage[i & 7];
            const float* rn = stage[(i + 1) & 7];

            if (tid < 100 && i + 5 < S_)
                cp_async16(&stage[(i + 5) & 7][tid * 4],
                           base + (size_t)(i + 5) * REC_ + tid * 4);
            CP_COMMIT();

            ull sw2 = *(const ull*)&swbuf[i & 1][v];

            ull a8[8], mk8[8];
            ld8(a8,  rc + 192 + ko);
            ld8(mk8, rc + 256 + ko);
            #pragma unroll
            for (int j = 0; j < 8; j++)
                Ha[j] = fma2(a8[j], Ha[j], mul2(mk8[j], sw2));

            // dots vs Ha with NEXT record's q, k, qa (2 chains each)
            ull qn8[8], kn8[8], yn8[8];
            ld8(qn8, rn + ko);
            ld8(kn8, rn + 64 + ko);
            ld8(yn8, rn + 128 + ko);
            ull aa0 = mul2(qn8[0], Ha[0]), aa1 = mul2(qn8[1], Ha[1]);
            ull cc0 = mul2(kn8[0], Ha[0]), cc1 = mul2(kn8[1], Ha[1]);
            ull yy0 = mul2(yn8[0], Ha[0]), yy1 = mul2(yn8[1], Ha[1]);
            #pragma unroll
            for (int j = 2; j < 8; j += 2) {
                aa0 = fma2(qn8[j],     Ha[j],     aa0);
                aa1 = fma2(qn8[j + 1], Ha[j + 1], aa1);
                cc0 = fma2(kn8[j],     Ha[j],     cc0);
                cc1 = fma2(kn8[j + 1], Ha[j + 1], cc1);
                yy0 = fma2(yn8[j],     Ha[j],     yy0);
                yy1 = fma2(yn8[j + 1], Ha[j + 1], yy1);
            }
            float2 fa0 = unpack2(aa0), fa1 = unpack2(aa1);
            float2 fc0 = unpack2(cc0), fc1 = unpack2(cc1);
            float2 fy0 = unpack2(yy0), fy1 = unpack2(yy1);
            float Ap = (fa0.x + fa0.y) + (fa1.x + fa1.y);
            float Cp = (fc0.x + fc0.y) + (fc1.x + fc1.y);
            float Yp = (fy0.x + fy0.y) + (fy1.x + fy1.y);

            part[(i + 1) & 1][v * 5 + kg] = make_float4(Ap, Cp, Yp, 0.0f);

            CP_WAIT3();
            BAR0();
        }
    } else {
        // ===== sequencer warp: partial sums + scalar chain + y =====
        const int lane = tid - 256;
        float w0 = 0.0f, w1 = 0.0f, sprev = 0.0f;

        for (int i = 0; i < S_; i++) {
            const float* rc = stage[i & 7];
            const float4* pp = part[i & 1];

            float4 x0 = pp[lane * 5 + 0], x1 = pp[lane * 5 + 1];
            float4 x2 = pp[lane * 5 + 2], x3 = pp[lane * 5 + 3];
            float4 z0 = pp[(lane + 32) * 5 + 0], z1 = pp[(lane + 32) * 5 + 1];
            float4 z2 = pp[(lane + 32) * 5 + 2], z3 = pp[(lane + 32) * 5 + 3];
            float A0 = (x0.x + x1.x) + (x2.x + x3.x);
            float C0 = (x0.y + x1.y) + (x2.y + x3.y);
            float Y0 = (x0.z + x1.z) + (x2.z + x3.z);
            float A1 = (z0.x + z1.x) + (z2.x + z3.x);
            float C1 = (z0.y + z1.y) + (z2.y + z3.y);
            float Y1 = (z0.z + z1.z) + (z2.z + z3.z);

            float v0 = rc[320 + lane], v1 = rc[352 + lane];
            float4 sc = *(const float4*)&rc[384];   // g, h, c, g2

            float sg = sprev * sc.x;
            float sh = sprev * sc.y;
            float u0 = v0 - A0 - sg * w0;
            float u1 = v1 - A1 - sg * w1;
            float e = u0 * u0 + u1 * u1;
            e += __shfl_xor_sync(~0u, e, 1);
            e += __shfl_xor_sync(~0u, e, 2);
            e += __shfl_xor_sync(~0u, e, 4);
            e += __shfl_xor_sync(~0u, e, 8);
            e += __shfl_xor_sync(~0u, e, 16);
            float s;
            asm("tanh.approx.f32 %0, %1;" : "=f"(s) : "f"(e * 0.499999495f));
            s = fmaf(0.5f, s, 0.5f);

            float t20 = sprev * sc.w * w0;          // sw_i * g2 (old w)
            float t21 = sprev * sc.w * w1;
            w0 = (v0 - C0) - sh * w0;
            w1 = (v1 - C1) - sh * w1;
            float y0 = Y0 + t20 + s * sc.z * w0;
            float y1 = Y1 + t21 + s * sc.z * w1;
            yb[(size_t)i * DS_ + lane]      = y0;
            yb[(size_t)i * DS_ + lane + 32] = y1;

            float sw0 = s * w0, sw1 = s * w1;
            swbuf[(i + 1) & 1][lane]      = make_float2(sw0, sw0);
            swbuf[(i + 1) & 1][lane + 32] = make_float2(sw1, sw1);
            sprev = s;
            BAR0();
        }
    }
}

// =====================================================================
// Kernel D: RMS-norm(y)*norm_w @ Wo^T -> out (proven)
// =====================================================================
__global__ void __launch_bounds__(256) out_gemm(
    const float* __restrict__ norm_w, const float* __restrict__ Wo,
    float* __restrict__ out)
{
    __shared__ __align__(16) float ys[32 * 64];
    __shared__ __align__(16) float wos[64 * 128];
    __shared__ float rs[32];
    __shared__ float nws[64];

    const int tid = threadIdx.x;
    const int m0 = blockIdx.y * 32;
    const int n0 = blockIdx.x * 128;

    for (int i = tid * 4; i < 2048; i += 1024)
        *(float4*)&ys[i] = *(const float4*)&g_y[(size_t)m0 * 64 + i];
    if (tid < 64) nws[tid] = norm_w[tid];
    {
        int n  = tid & 127;
        int vb = tid >> 7;
        #pragma unroll
        for (int q = 0; q < 8; q++) {
            int v4 = vb * 8 + q;
            float4 w = *(const float4*)&Wo[(size_t)(n0 + n) * 64 + v4 * 4];
            wos[(v4 * 4 + 0) * 128 + n] = w.x;
            wos[(v4 * 4 + 1) * 128 + n] = w.y;
            wos[(v4 * 4 + 2) * 128 + n] = w.z;
            wos[(v4 * 4 + 3) * 128 + n] = w.w;
        }
    }
    __syncthreads();

    {
        int r = tid >> 3, p = tid & 7;
        float sum = 0.0f;
        #pragma unroll
        for (int j = 0; j < 8; j++) { float x = ys[r * 64 + p * 8 + j]; sum += x * x; }
        sum += __shfl_xor_sync(~0u, sum, 1);
        sum += __shfl_xor_sync(~0u, sum, 2);
        sum += __shfl_xor_sync(~0u, sum, 4);
        if (p == 0) rs[r] = rsqrtf(sum * (1.0f / 64.0f) + 1e-6f);
    }
    __syncthreads();
    for (int i = tid; i < 2048; i += 256)
        ys[i] = ys[i] * rs[i >> 6] * nws[i & 63];
    __syncthreads();

    const int tn = tid & 31;
    const int tm = tid >> 5;
    float acc[4][4];
    #pragma unroll
    for (int i = 0; i < 4; i++)
        #pragma unroll
        for (int j = 0; j < 4; j++) acc[i][j] = 0.0f;

    #pragma unroll 8
    for (int vv = 0; vv < 64; vv++) {
        float b0 = wos[vv * 128 + tn];
        float b1 = wos[vv * 128 + tn + 32];
        float b2 = wos[vv * 128 + tn + 64];
        float b3 = wos[vv * 128 + tn + 96];
        #pragma unroll
        for (int i = 0; i < 4; i++) {
            float a = ys[(tm * 4 + i) * 64 + vv];
            acc[i][0] += a * b0; acc[i][1] += a * b1;
            acc[i][2] += a * b2; acc[i][3] += a * b3;
        }
    }
    #pragma unroll
    for (int i = 0; i < 4; i++) {
        size_t row = (size_t)(m0 + tm * 4 + i) * 2048 + n0 + tn;
        #pragma unroll
        for (int j = 0; j < 4; j++) out[row + 32 * j] = acc[i][j];
    }
}

// =====================================================================
extern "C" void kernel_launch(void* const* d_in, const int* in_sizes, int n_in,
                              void* d_out, int out_size)
{
    const float* x      = (const float*)d_in[0];
    const float* Wk     = (const float*)d_in[1];
    const float* Wv     = (const float*)d_in[2];
    const float* Wq     = (const float*)d_in[3];
    const float* Wa_w   = (const float*)d_in[4];
    const float* Wa_b   = (const float*)d_in[5];
    const float* lam    = (const float*)d_in[6];
    const float* norm_w = (const float*)d_in[7];
    const float* Wo     = (const float*)d_in[8];
    float* out = (float*)d_out;

    proj_gemm<<<dim3(128, 4), 256>>>(x, Wk, Wv, Wq, Wa_w);
    prep_kernel<<<1024, 256>>>(Wa_b, lam);
    ghc_kernel<<<1024, 256>>>();
    scan_kernel<<<4, 288>>>();
    out_gemm<<<dim3(16, 256), 256>>>(norm_w, Wo, out);
}

// round 8
// speedup vs baseline: 2.3218x; 1.5338x over previous
#include <cuda_runtime.h>
#include <cstdint>

typedef unsigned long long ull;

#define B_   4
#define S_   2048
#define DM_  2048
#define DS_  64
#define REC_ 336   // q[0:64] k[64:128] a[128:192] km[192:256] v[256:320] g,h,c,g2[320:324] pad->336

// ---------------- f32x2 packed helpers ----------------
__device__ __forceinline__ ull fma2(ull a, ull b, ull c) {
    ull d; asm("fma.rn.f32x2 %0,%1,%2,%3;" : "=l"(d) : "l"(a), "l"(b), "l"(c)); return d;
}
__device__ __forceinline__ ull mul2(ull a, ull b) {
    ull d; asm("mul.rn.f32x2 %0,%1,%2;" : "=l"(d) : "l"(a), "l"(b)); return d;
}
__device__ __forceinline__ ull pack2(float lo, float hi) {
    ull d; asm("mov.b64 %0, {%1,%2};" : "=l"(d) : "f"(lo), "f"(hi)); return d;
}
__device__ __forceinline__ float2 unpack2(ull a) {
    float lo, hi; asm("mov.b64 {%0,%1}, %2;" : "=f"(lo), "=f"(hi) : "l"(a));
    return make_float2(lo, hi);
}

// ---------------- cp.async ----------------
__device__ __forceinline__ void cp_async16(void* smem, const void* gmem) {
    uint32_t s = (uint32_t)__cvta_generic_to_shared(smem);
    asm volatile("cp.async.cg.shared.global [%0], [%1], 16;" :: "r"(s), "l"(gmem) : "memory");
}
#define CP_COMMIT()  asm volatile("cp.async.commit_group;" ::: "memory")
#define CP_WAIT3()   asm volatile("cp.async.wait_group 3;" ::: "memory")
#define BAR0()       asm volatile("bar.sync 0;" ::: "memory")

// ---------------- scratch ----------------
__device__ float g_raw[B_ * S_ * 256];
__device__ float g_inp[B_ * S_ * REC_];
__device__ float g_y  [B_ * S_ * DS_];

// =====================================================================
// Kernel A: projection GEMM (proven)
// =====================================================================
#define BM 64
#define BN 64
#define BK 32

__global__ void __launch_bounds__(256) proj_gemm(
    const float* __restrict__ x,
    const float* __restrict__ Wk, const float* __restrict__ Wv,
    const float* __restrict__ Wq, const float* __restrict__ Wa)
{
    __shared__ __align__(16) float As[BK][BM + 4];
    __shared__ __align__(16) float Bs[BK][BN + 4];

    const int mt = blockIdx.x;
    const int nt = blockIdx.y;
    const float* W = (nt == 0) ? Wk : (nt == 1) ? Wv : (nt == 2) ? Wq : Wa;

    const int tid  = threadIdx.x;
    const int lrow = tid >> 2;
    const int lk   = (tid & 3) * 4;
    const float* xg = x + (size_t)(mt * BM + lrow) * DM_ + lk;
    const float* wg = W + (size_t)lrow * DM_ + lk;

    const int tn4 = (tid & 15) * 4;
    const int tm4 = (tid >> 4) * 4;

    ull acc[4][2];
    #pragma unroll
    for (int i = 0; i < 4; i++) { acc[i][0] = 0ull; acc[i][1] = 0ull; }

    float4 av0 = *(const float4*)xg;
    float4 av1 = *(const float4*)(xg + 16);
    float4 bv0 = *(const float4*)wg;
    float4 bv1 = *(const float4*)(wg + 16);

    for (int k0 = 0; k0 < DM_; k0 += BK) {
        __syncthreads();
        As[lk + 0][lrow] = av0.x; As[lk + 1][lrow] = av0.y;
        As[lk + 2][lrow] = av0.z; As[lk + 3][lrow] = av0.w;
        As[lk + 16][lrow] = av1.x; As[lk + 17][lrow] = av1.y;
        As[lk + 18][lrow] = av1.z; As[lk + 19][lrow] = av1.w;
        Bs[lk + 0][lrow] = bv0.x; Bs[lk + 1][lrow] = bv0.y;
        Bs[lk + 2][lrow] = bv0.z; Bs[lk + 3][lrow] = bv0.w;
        Bs[lk + 16][lrow] = bv1.x; Bs[lk + 17][lrow] = bv1.y;
        Bs[lk + 18][lrow] = bv1.z; Bs[lk + 19][lrow] = bv1.w;
        if (k0 + BK < DM_) {
            av0 = *(const float4*)(xg + k0 + BK);
            av1 = *(const float4*)(xg + k0 + BK + 16);
            bv0 = *(const float4*)(wg + k0 + BK);
            bv1 = *(const float4*)(wg + k0 + BK + 16);
        }
        __syncthreads();
        #pragma unroll
        for (int kk = 0; kk < BK; kk++) {
            ulonglong2 bb = *(const ulonglong2*)&Bs[kk][tn4];
            float4 a4 = *(const float4*)&As[kk][tm4];
            ull p0 = pack2(a4.x, a4.x), p1 = pack2(a4.y, a4.y);
            ull p2 = pack2(a4.z, a4.z), p3 = pack2(a4.w, a4.w);
            acc[0][0] = fma2(p0, bb.x, acc[0][0]); acc[0][1] = fma2(p0, bb.y, acc[0][1]);
            acc[1][0] = fma2(p1, bb.x, acc[1][0]); acc[1][1] = fma2(p1, bb.y, acc[1][1]);
            acc[2][0] = fma2(p2, bb.x, acc[2][0]); acc[2][1] = fma2(p2, bb.y, acc[2][1]);
            acc[3][0] = fma2(p3, bb.x, acc[3][0]); acc[3][1] = fma2(p3, bb.y, acc[3][1]);
        }
    }

    #pragma unroll
    for (int i = 0; i < 4; i++) {
        int m = mt * BM + tm4 + i;
        #pragma unroll
        for (int j = 0; j < 2; j++) {
            float2 f = unpack2(acc[i][j]);
            *(float2*)&g_raw[(size_t)m * 256 + nt * 64 + tn4 + 2 * j] = f;
        }
    }
}

// =====================================================================
// Kernel B: per-token prep. Record: q, k, a, km, v ; c scalar.
// =====================================================================
__global__ void __launch_bounds__(256) prep_kernel(
    const float* __restrict__ Wa_b, const float* __restrict__ lam)
{
    const int g    = blockIdx.x * 8 + (threadIdx.x >> 5);
    const int lane = threadIdx.x & 31;
    const float* r_ = g_raw + (size_t)g * 256;

    float k0 = r_[lane],        k1 = r_[lane + 32];
    float v0 = r_[64 + lane],   v1 = r_[96 + lane];
    float q0 = r_[128 + lane],  q1 = r_[160 + lane];
    float z0 = r_[192 + lane] + Wa_b[lane];
    float z1 = r_[224 + lane] + Wa_b[lane + 32];

    float kn = k0 * k0 + k1 * k1;
    #pragma unroll
    for (int m = 1; m < 32; m <<= 1) kn += __shfl_xor_sync(~0u, kn, m);
    float kinv = 1.0f / fmaxf(sqrtf(kn), 1e-12f);
    k0 *= kinv; k1 *= kinv;

    float qn = q0 * q0 + q1 * q1;
    #pragma unroll
    for (int m = 1; m < 32; m <<= 1) qn += __shfl_xor_sync(~0u, qn, m);
    float qinv = 1.0f / fmaxf(sqrtf(qn), 1e-12f);
    q0 *= qinv; q1 *= qinv;

    float la0 = logf(1.0f / (1.0f + expf(-lam[lane])) + 1e-8f);
    float la1 = logf(1.0f / (1.0f + expf(-lam[lane + 32])) + 1e-8f);
    float rr0 = 1.0f / (1.0f + expf(-z0));
    float rr1 = 1.0f / (1.0f + expf(-z1));
    float al0 = expf(8.0f * rr0 * la0);
    float al1 = expf(8.0f * rr1 * la1);
    float km0 = k0 * (1.0f - al0), km1 = k1 * (1.0f - al1);

    float c = q0 * km0 + q1 * km1;
    #pragma unroll
    for (int m = 1; m < 32; m <<= 1) c += __shfl_xor_sync(~0u, c, m);

    float* o = g_inp + (size_t)g * REC_;
    o[lane] = q0;          o[lane + 32] = q1;
    o[64 + lane] = k0;     o[96 + lane] = k1;
    o[128 + lane] = al0;   o[160 + lane] = al1;
    o[192 + lane] = km0;   o[224 + lane] = km1;
    o[256 + lane] = v0;    o[288 + lane] = v1;
    if (lane == 0) o[322] = c;
}

// =====================================================================
// Kernel B2: scalars vs km_{t-1}: g = q.km', h = k.km', g2 = (q.a).km'
// =====================================================================
__global__ void __launch_bounds__(256) ghc_kernel()
{
    const int g    = blockIdx.x * 8 + (threadIdx.x >> 5);
    const int lane = threadIdx.x & 31;
    const int t    = g & (S_ - 1);
    float* cur = g_inp + (size_t)g * REC_;

    float m0 = 0.0f, m1 = 0.0f;
    if (t > 0) {
        const float* prev = cur - REC_;
        m0 = prev[192 + lane]; m1 = prev[224 + lane];
    }
    float q0 = cur[lane],        q1 = cur[lane + 32];
    float k0 = cur[64 + lane],   k1 = cur[96 + lane];
    float a0 = cur[128 + lane],  a1 = cur[160 + lane];

    float gq = q0 * m0 + q1 * m1;
    float gh = k0 * m0 + k1 * m1;
    float g2 = q0 * a0 * m0 + q1 * a1 * m1;
    #pragma unroll
    for (int m = 1; m < 32; m <<= 1) {
        gq += __shfl_xor_sync(~0u, gq, m);
        gh += __shfl_xor_sync(~0u, gh, m);
        g2 += __shfl_xor_sync(~0u, g2, m);
    }
    if (lane == 0) { cur[320] = gq; cur[321] = gh; cur[323] = g2; }
}

// =====================================================================
// Kernel C: warp-specialized scan. 4 CTAs x 288 threads.
// Vector thread owns 2 v's x 8 k's; a_i, km_{i-1} carried in registers.
// =====================================================================
__device__ __forceinline__ void ld4(ull* d, const float* p) {
    ulonglong2 t0 = *(const ulonglong2*)(p);
    ulonglong2 t1 = *(const ulonglong2*)(p + 4);
    d[0] = t0.x; d[1] = t0.y; d[2] = t1.x; d[3] = t1.y;
}

__global__ void __launch_bounds__(288, 1) scan_kernel()
{
    __shared__ __align__(16) float  stage[8][REC_];
    __shared__ __align__(16) float4 part[2][64 * 9];   // [buf][v*9 + kg], stride-9 pad
    __shared__ __align__(16) float2 swbuf[2][64];      // (sw, sw) per v

    const int b   = blockIdx.x;
    const int tid = threadIdx.x;
    const float* base = g_inp + (size_t)b * S_ * REC_;
    float* yb = g_y + (size_t)b * S_ * DS_;

    if (tid < 64) swbuf[0][tid] = make_float2(0.0f, 0.0f);
    for (int i = tid; i < 64 * 9; i += 288)
        part[0][i] = make_float4(0.f, 0.f, 0.f, 0.f);

    #pragma unroll
    for (int t = 0; t < 6; t++) {
        if (tid < 84) cp_async16(&stage[t][tid * 4], base + (size_t)t * REC_ + tid * 4);
        CP_COMMIT();
    }
    CP_WAIT3();          // records 0..2 ready
    __syncthreads();

    if (tid < 256) {
        // ===== vector warps =====
        const int kg = tid & 7;
        const int vp = tid >> 3;
        const int v0 = vp * 2;
        const int ko = kg * 8;

        ull Ha0[4], Ha1[4], ac[4], kmp[4];
        ld4(ac, stage[0] + 128 + ko);      // a_0
        #pragma unroll
        for (int j = 0; j < 4; j++) { Ha0[j] = 0ull; Ha1[j] = 0ull; kmp[j] = 0ull; }

        for (int i = 0; i < S_; i++) {
            const float* rc = stage[i & 7];
            const float* rn = stage[(i + 1) & 7];

            if (tid < 84 && i + 6 < S_)
                cp_async16(&stage[(i + 6) & 7][tid * 4],
                           base + (size_t)(i + 6) * REC_ + tid * 4);
            CP_COMMIT();

            // sw for both v's: one LDS.128 (v0 even)
            ulonglong2 swp = *(const ulonglong2*)&swbuf[i & 1][v0];

            // Ha_i = a_i (.) (Ha_{i-1} + sw_i * km_{i-1})
            #pragma unroll
            for (int j = 0; j < 4; j++) {
                Ha0[j] = mul2(ac[j], fma2(kmp[j], swp.x, Ha0[j]));
                Ha1[j] = mul2(ac[j], fma2(kmp[j], swp.y, Ha1[j]));
            }

            // loads: km_i (rc), q/k/a of record i+1 (rn)
            ull kmn[4], qn[4], knn[4], an[4];
            ld4(kmn, rc + 192 + ko);
            ld4(qn,  rn + ko);
            ld4(knn, rn + 64 + ko);
            ld4(an,  rn + 128 + ko);
            ull qa0 = mul2(qn[0], an[0]), qa1 = mul2(qn[1], an[1]);
            ull qa2 = mul2(qn[2], an[2]), qa3 = mul2(qn[3], an[3]);

            // dots vs Ha_i for both v's: A=q., C=k., Y=qa.
            ull A0 = mul2(qn[0], Ha0[0]), A1 = mul2(qn[0], Ha1[0]);
            ull C0 = mul2(knn[0], Ha0[0]), C1 = mul2(knn[0], Ha1[0]);
            ull Y0 = mul2(qa0, Ha0[0]),   Y1 = mul2(qa0, Ha1[0]);
            A0 = fma2(qn[1], Ha0[1], A0);  A1 = fma2(qn[1], Ha1[1], A1);
            C0 = fma2(knn[1], Ha0[1], C0); C1 = fma2(knn[1], Ha1[1], C1);
            Y0 = fma2(qa1, Ha0[1], Y0);    Y1 = fma2(qa1, Ha1[1], Y1);
            A0 = fma2(qn[2], Ha0[2], A0);  A1 = fma2(qn[2], Ha1[2], A1);
            C0 = fma2(knn[2], Ha0[2], C0); C1 = fma2(knn[2], Ha1[2], C1);
            Y0 = fma2(qa2, Ha0[2], Y0);    Y1 = fma2(qa2, Ha1[2], Y1);
            A0 = fma2(qn[3], Ha0[3], A0);  A1 = fma2(qn[3], Ha1[3], A1);
            C0 = fma2(knn[3], Ha0[3], C0); C1 = fma2(knn[3], Ha1[3], C1);
            Y0 = fma2(qa3, Ha0[3], Y0);    Y1 = fma2(qa3, Ha1[3], Y1);

            float2 fa0 = unpack2(A0), fc0 = unpack2(C0), fy0 = unpack2(Y0);
            float2 fa1 = unpack2(A1), fc1 = unpack2(C1), fy1 = unpack2(Y1);
            part[(i + 1) & 1][v0 * 9 + kg] =
                make_float4(fa0.x + fa0.y, fc0.x + fc0.y, fy0.x + fy0.y, 0.0f);
            part[(i + 1) & 1][v0 * 9 + 9 + kg] =
                make_float4(fa1.x + fa1.y, fc1.x + fc1.y, fy1.x + fy1.y, 0.0f);

            #pragma unroll
            for (int j = 0; j < 4; j++) { ac[j] = an[j]; kmp[j] = kmn[j]; }

            CP_WAIT3();
            BAR0();
        }
    } else {
        // ===== sequencer warp =====
        const int lane = tid - 256;
        float w0 = 0.0f, w1 = 0.0f, sprev = 0.0f;

        for (int i = 0; i < S_; i++) {
            const float* rc = stage[i & 7];
            const float4* pp = part[i & 1];

            float4 x0 = pp[lane * 9 + 0], x1 = pp[lane * 9 + 1];
            float4 x2 = pp[lane * 9 + 2], x3 = pp[lane * 9 + 3];
            float4 x4 = pp[lane * 9 + 4], x5 = pp[lane * 9 + 5];
            float4 x6 = pp[lane * 9 + 6], x7 = pp[lane * 9 + 7];
            float4 z0 = pp[(lane + 32) * 9 + 0], z1 = pp[(lane + 32) * 9 + 1];
            float4 z2 = pp[(lane + 32) * 9 + 2], z3 = pp[(lane + 32) * 9 + 3];
            float4 z4 = pp[(lane + 32) * 9 + 4], z5 = pp[(lane + 32) * 9 + 5];
            float4 z6 = pp[(lane + 32) * 9 + 6], z7 = pp[(lane + 32) * 9 + 7];

            float A0 = ((x0.x + x1.x) + (x2.x + x3.x)) + ((x4.x + x5.x) + (x6.x + x7.x));
            float C0 = ((x0.y + x1.y) + (x2.y + x3.y)) + ((x4.y + x5.y) + (x6.y + x7.y));
            float Y0 = ((x0.z + x1.z) + (x2.z + x3.z)) + ((x4.z + x5.z) + (x6.z + x7.z));
            float A1 = ((z0.x + z1.x) + (z2.x + z3.x)) + ((z4.x + z5.x) + (z6.x + z7.x));
            float C1 = ((z0.y + z1.y) + (z2.y + z3.y)) + ((z4.y + z5.y) + (z6.y + z7.y));
            float Y1 = ((z0.z + z1.z) + (z2.z + z3.z)) + ((z4.z + z5.z) + (z6.z + z7.z));

            float v0 = rc[256 + lane], v1 = rc[288 + lane];
            float4 sc = *(const float4*)&rc[320];   // g, h, c, g2

            float sg = sprev * sc.x;
            float sh = sprev * sc.y;
            float u0 = v0 - A0 - sg * w0;
            float u1 = v1 - A1 - sg * w1;
            float e = u0 * u0 + u1 * u1;
            e += __shfl_xor_sync(~0u, e, 1);
            e += __shfl_xor_sync(~0u, e, 2);
            e += __shfl_xor_sync(~0u, e, 4);
            e += __shfl_xor_sync(~0u, e, 8);
            e += __shfl_xor_sync(~0u, e, 16);
            float s;
            asm("tanh.approx.f32 %0, %1;" : "=f"(s) : "f"(e * 0.499999495f));
            s = fmaf(0.5f, s, 0.5f);

            float t20 = sprev * sc.w * w0;
            float t21 = sprev * sc.w * w1;
            w0 = (v0 - C0) - sh * w0;
            w1 = (v1 - C1) - sh * w1;
            yb[(size_t)i * DS_ + lane]      = Y0 + t20 + s * sc.z * w0;
            yb[(size_t)i * DS_ + lane + 32] = Y1 + t21 + s * sc.z * w1;

            float sw0 = s * w0, sw1 = s * w1;
            swbuf[(i + 1) & 1][lane]      = make_float2(sw0, sw0);
            swbuf[(i + 1) & 1][lane + 32] = make_float2(sw1, sw1);
            sprev = s;
            BAR0();
        }
    }
}

// =====================================================================
// Kernel D: RMS-norm(y)*norm_w @ Wo^T -> out (proven)
// =====================================================================
__global__ void __launch_bounds__(256) out_gemm(
    const float* __restrict__ norm_w, const float* __restrict__ Wo,
    float* __restrict__ out)
{
    __shared__ __align__(16) float ys[32 * 64];
    __shared__ __align__(16) float wos[64 * 128];
    __shared__ float rs[32];
    __shared__ float nws[64];

    const int tid = threadIdx.x;
    const int m0 = blockIdx.y * 32;
    const int n0 = blockIdx.x * 128;

    for (int i = tid * 4; i < 2048; i += 1024)
        *(float4*)&ys[i] = *(const float4*)&g_y[(size_t)m0 * 64 + i];
    if (tid < 64) nws[tid] = norm_w[tid];
    {
        int n  = tid & 127;
        int vb = tid >> 7;
        #pragma unroll
        for (int q = 0; q < 8; q++) {
            int v4 = vb * 8 + q;
            float4 w = *(const float4*)&Wo[(size_t)(n0 + n) * 64 + v4 * 4];
            wos[(v4 * 4 + 0) * 128 + n] = w.x;
            wos[(v4 * 4 + 1) * 128 + n] = w.y;
            wos[(v4 * 4 + 2) * 128 + n] = w.z;
            wos[(v4 * 4 + 3) * 128 + n] = w.w;
        }
    }
    __syncthreads();

    {
        int r = tid >> 3, p = tid & 7;
        float sum = 0.0f;
        #pragma unroll
        for (int j = 0; j < 8; j++) { float x = ys[r * 64 + p * 8 + j]; sum += x * x; }
        sum += __shfl_xor_sync(~0u, sum, 1);
        sum += __shfl_xor_sync(~0u, sum, 2);
        sum += __shfl_xor_sync(~0u, sum, 4);
        if (p == 0) rs[r] = rsqrtf(sum * (1.0f / 64.0f) + 1e-6f);
    }
    __syncthreads();
    for (int i = tid; i < 2048; i += 256)
        ys[i] = ys[i] * rs[i >> 6] * nws[i & 63];
    __syncthreads();

    const int tn = tid & 31;
    const int tm = tid >> 5;
    float acc[4][4];
    #pragma unroll
    for (int i = 0; i < 4; i++)
        #pragma unroll
        for (int j = 0; j < 4; j++) acc[i][j] = 0.0f;

    #pragma unroll 8
    for (int vv = 0; vv < 64; vv++) {
        float b0 = wos[vv * 128 + tn];
        float b1 = wos[vv * 128 + tn + 32];
        float b2 = wos[vv * 128 + tn + 64];
        float b3 = wos[vv * 128 + tn + 96];
        #pragma unroll
        for (int i = 0; i < 4; i++) {
            float a = ys[(tm * 4 + i) * 64 + vv];
            acc[i][0] += a * b0; acc[i][1] += a * b1;
            acc[i][2] += a * b2; acc[i][3] += a * b3;
        }
    }
    #pragma unroll
    for (int i = 0; i < 4; i++) {
        size_t row = (size_t)(m0 + tm * 4 + i) * 2048 + n0 + tn;
        #pragma unroll
        for (int j = 0; j < 4; j++) out[row + 32 * j] = acc[i][j];
    }
}

// =====================================================================
extern "C" void kernel_launch(void* const* d_in, const int* in_sizes, int n_in,
                              void* d_out, int out_size)
{
    const float* x      = (const float*)d_in[0];
    const float* Wk     = (const float*)d_in[1];
    const float* Wv     = (const float*)d_in[2];
    const float* Wq     = (const float*)d_in[3];
    const float* Wa_w   = (const float*)d_in[4];
    const float* Wa_b   = (const float*)d_in[5];
    const float* lam    = (const float*)d_in[6];
    const float* norm_w = (const float*)d_in[7];
    const float* Wo     = (const float*)d_in[8];
    float* out = (float*)d_out;

    proj_gemm<<<dim3(128, 4), 256>>>(x, Wk, Wv, Wq, Wa_w);
    prep_kernel<<<1024, 256>>>(Wa_b, lam);
    ghc_kernel<<<1024, 256>>>();
    scan_kernel<<<4, 288>>>();
    out_gemm<<<dim3(16, 256), 256>>>(norm_w, Wo, out);
}